// round 4
// baseline (speedup 1.0000x reference)
#include <cuda_runtime.h>
#include <cuda_bf16.h>

#define BINS 256
#define NWARPS 8            // blockDim = 256 -> 8 warps, one private smem histogram per warp
#define HIST_BLOCKS 912     // 152 SMs x 6 blocks -> exactly one wave at occupancy 6
#define HIST_THREADS 256

// Scratch (device globals -> no allocation). Zero-initialized at module load;
// the last block resets them every launch, so every graph replay starts clean.
__device__ unsigned int g_hist[BINS];
__device__ unsigned int g_ticket;

__device__ __forceinline__ void bin_one(float x, unsigned int* warp_hist) {
    // torch.histc: bins over [LO,HI]=[-4,4]; x==HI -> last bin; outside ignored.
    if (x >= -4.0f && x <= 4.0f) {
        float t = (x - (-4.0f)) * 32.0f;   // sub-then-mul, matches reference rounding
        int idx = __float2int_rd(t);        // single F2I.FLOOR
        idx = min(idx, BINS - 1);
        atomicAdd(&warp_hist[idx], 1u);
    }
}

__device__ __forceinline__ void bin4(float4 v, unsigned int* wh) {
    bin_one(v.x, wh);
    bin_one(v.y, wh);
    bin_one(v.z, wh);
    bin_one(v.w, wh);
}

__global__ void __launch_bounds__(HIST_THREADS, 6)
hist_kernel(const float* __restrict__ x, long long n,
            float* __restrict__ out, int out_size) {
    __shared__ unsigned int sh[NWARPS][BINS];
    __shared__ bool is_last;
    const int tid  = threadIdx.x;
    const int warp = tid >> 5;
    unsigned int* wh = sh[warp];

    // Zero shared histograms
    #pragma unroll
    for (int i = tid; i < NWARPS * BINS; i += HIST_THREADS)
        ((unsigned int*)sh)[i] = 0u;
    __syncthreads();

    const long long n4 = n >> 2;
    const float4* __restrict__ x4 = (const float4*)x;
    const long long stride = (long long)gridDim.x * HIST_THREADS;
    long long i = (long long)blockIdx.x * HIST_THREADS + tid;

    // Main loop: 8 independent LDG.128 front-batched per iteration (MLP_p1 = 8)
    for (; i + 7 * stride < n4; i += 8 * stride) {
        float4 a = x4[i];
        float4 b = x4[i + stride];
        float4 c = x4[i + 2 * stride];
        float4 d = x4[i + 3 * stride];
        float4 e = x4[i + 4 * stride];
        float4 f = x4[i + 5 * stride];
        float4 g = x4[i + 6 * stride];
        float4 h = x4[i + 7 * stride];
        bin4(a, wh); bin4(b, wh); bin4(c, wh); bin4(d, wh);
        bin4(e, wh); bin4(f, wh); bin4(g, wh); bin4(h, wh);
    }
    // Remainder float4s
    for (; i < n4; i += stride)
        bin4(x4[i], wh);

    // Scalar tail (n not multiple of 4) — block 0 only
    if (blockIdx.x == 0) {
        for (long long j = (n4 << 2) + tid; j < n; j += HIST_THREADS)
            bin_one(x[j], wh);
    }
    __syncthreads();

    // Reduce per-warp copies, one gmem atomic per bin per block
    for (int b = tid; b < BINS; b += HIST_THREADS) {
        unsigned int s = 0;
        #pragma unroll
        for (int c = 0; c < NWARPS; c++) s += sh[c][b];
        if (s) atomicAdd(&g_hist[b], s);
    }

    // Last-block-done protocol: final block writes the output and resets state.
    __threadfence();
    __syncthreads();
    if (tid == 0)
        is_last = (atomicAdd(&g_ticket, 1u) == (unsigned)gridDim.x - 1u);
    __syncthreads();

    if (is_last) {
        __threadfence();                 // make all blocks' g_hist atomics visible
        unsigned int v = g_hist[tid];
        g_hist[tid] = 0u;                // reset for next graph replay
        if (tid == 0) g_ticket = 0u;
        float fv = (float)v;
        // Reference returns (h, h): fill every 256-element chunk of out.
        for (int base = 0; base + tid < out_size; base += BINS)
            out[base + tid] = fv;
    }
}

extern "C" void kernel_launch(void* const* d_in, const int* in_sizes, int n_in,
                              void* d_out, int out_size) {
    const float* x = (const float*)d_in[0];
    long long n = (long long)in_sizes[0];
    float* out = (float*)d_out;

    hist_kernel<<<HIST_BLOCKS, HIST_THREADS>>>(x, n, out, out_size);
}